// round 1
// baseline (speedup 1.0000x reference)
#include <cuda_runtime.h>

// RNN: h_t = tanh(x_t @ W_ih^T + b_ih + b_hh + h_{t-1} @ W_hh^T), return h_{T-1}
// B=4096, T=512, INPUT=15, HIDDEN=20.
// One thread per (batch, hidden_unit). h exchanged via double-buffered smem,
// one __syncthreads per timestep. x staged to smem with distance-1 prefetch.

#define T_STEPS 512
#define BATCH   4096
#define N_IN    15
#define N_HID   20
#define BSUB    14                    // batches per CTA
#define THREADS (BSUB * N_HID)        // 280
#define N_CTAS  ((BATCH + BSUB - 1) / BSUB)   // 293

__global__ __launch_bounds__(THREADS, 2)
void rnn_fused_kernel(const float* __restrict__ feature,
                      const float* __restrict__ W_ih,
                      const float* __restrict__ W_hh,
                      const float* __restrict__ b_ih,
                      const float* __restrict__ b_hh,
                      float* __restrict__ out)
{
    // double-buffered staging: x tile (16 floats, 15 used) and h vector (24, 20 used)
    __shared__ __align__(16) float xs[2][BSUB][16];
    __shared__ __align__(16) float hs[2][BSUB][24];

    const int tid = threadIdx.x;
    const int bs  = tid / N_HID;      // local batch 0..13
    const int j   = tid % N_HID;      // hidden unit 0..19
    const int b   = blockIdx.x * BSUB + bs;
    const bool valid = (b < BATCH);

    // ---- resident weights: row j of W_ih and W_hh, fused bias ----
    float wih[N_IN];
#pragma unroll
    for (int k = 0; k < N_IN; k++)  wih[k] = W_ih[j * N_IN + k];
    float whh[N_HID];
#pragma unroll
    for (int k = 0; k < N_HID; k++) whh[k] = W_hh[j * N_HID + k];
    const float bias = b_ih[j] + b_hh[j];

    // ---- prologue: h_{-1} = 0, stage x_0 into buffer 0 ----
    hs[0][bs][j] = 0.0f;
    const float* xrow = feature + (size_t)(valid ? b : 0) * T_STEPS * N_IN;
    if (j < N_IN) {
        xs[0][bs][j] = valid ? __ldg(xrow + j) : 0.0f;
    }

    float h = 0.0f;

#pragma unroll 2
    for (int t = 0; t < T_STEPS; t++) {
        const int p = t & 1;
        __syncthreads();   // xs[p], hs[p] ready; previous readers of xs[p^1]/hs[p^1] done

        // prefetch x_{t+1} (independent of compute below; issued early)
        float xnext = 0.0f;
        if (j < N_IN && (t + 1) < T_STEPS) {
            xnext = __ldg(xrow + (t + 1) * N_IN + j);
        }

        // gather x_t (broadcast LDS.128 x4) and h_{t-1} (LDS.128 x5)
        float xl[16];
        {
            const float4* xv = (const float4*)xs[p][bs];
            float4 v0 = xv[0], v1 = xv[1], v2 = xv[2], v3 = xv[3];
            *(float4*)&xl[0]  = v0; *(float4*)&xl[4]  = v1;
            *(float4*)&xl[8]  = v2; *(float4*)&xl[12] = v3;
        }
        float hl[20];
        {
            const float4* hv = (const float4*)hs[p][bs];
            float4 v0 = hv[0], v1 = hv[1], v2 = hv[2], v3 = hv[3], v4 = hv[4];
            *(float4*)&hl[0]  = v0; *(float4*)&hl[4]  = v1;
            *(float4*)&hl[8]  = v2; *(float4*)&hl[12] = v3;
            *(float4*)&hl[16] = v4;
        }

        // 35 FMAs split over 4 accumulators (ILP)
        float a0 = bias, a1 = 0.0f, a2 = 0.0f, a3 = 0.0f;
#pragma unroll
        for (int k = 0; k < N_IN; k++) {
            float* a = (k & 3) == 0 ? &a0 : (k & 3) == 1 ? &a1 : (k & 3) == 2 ? &a2 : &a3;
            *a = fmaf(xl[k], wih[k], *a);
        }
#pragma unroll
        for (int k = 0; k < N_HID; k++) {
            float* a = (k & 3) == 0 ? &a0 : (k & 3) == 1 ? &a1 : (k & 3) == 2 ? &a2 : &a3;
            *a = fmaf(hl[k], whh[k], *a);
        }
        const float acc = (a0 + a1) + (a2 + a3);

        // tanh(x) = 1 - 2/(exp(2x)+1)   (2x MUFU, ~1e-6 rel err, handles +-inf)
        const float e = __expf(2.0f * acc);
        h = 1.0f - __fdividef(2.0f, e + 1.0f);

        // publish into the other buffer; next-iter barrier makes it visible
        hs[p ^ 1][bs][j] = h;
        if (j < N_IN) xs[p ^ 1][bs][j] = xnext;
    }

    if (valid) out[b * N_HID + j] = h;
}

extern "C" void kernel_launch(void* const* d_in, const int* in_sizes, int n_in,
                              void* d_out, int out_size)
{
    const float* feature = (const float*)d_in[0];
    const float* W_ih    = (const float*)d_in[1];
    const float* W_hh    = (const float*)d_in[2];
    const float* b_ih    = (const float*)d_in[3];
    const float* b_hh    = (const float*)d_in[4];
    float* out = (float*)d_out;

    rnn_fused_kernel<<<N_CTAS, THREADS>>>(feature, W_ih, W_hh, b_ih, b_hh, out);
}